// round 14
// baseline (speedup 1.0000x reference)
#include <cuda_runtime.h>
#include <cuda_bf16.h>
#include <math.h>

// Problem constants
#define BB   2
#define TT   2048
#define CC   2048
#define NH   16
#define HD   128
#define MM   (BB*TT)        // 4096
#define N_QKV (3*CC)        // 6144

// ---------------------------------------------------------------------------
// Scratch (device globals; no runtime allocation)
// ---------------------------------------------------------------------------
__device__ float g_q[(size_t)BB*NH*TT*HD];   // [B,H,T,hd], q pre-scaled, tf32 bits
__device__ float g_k[(size_t)BB*NH*TT*HD];   // [B,H,T,hd], tf32 bits
__device__ float g_vt[(size_t)BB*NH*HD*TT];  // [B,H,hd,T]  V TRANSPOSED, tf32 bits
__device__ float g_y[(size_t)BB*TT*CC];      // tf32 bits
__device__ float g_x[(size_t)MM*CC];         // tf32 bits
__device__ float g_wa[(size_t)CC*N_QKV];     // tf32 bits, W_attn^T [N_QKV][CC]
__device__ float g_wp[(size_t)CC*CC];        // tf32 bits, W_proj^T [CC][CC]

// ---------------------------------------------------------------------------
// TF32 / math helpers
// ---------------------------------------------------------------------------
__device__ __forceinline__ unsigned f2tf(float x) {
    unsigned r;
    asm("cvt.rna.tf32.f32 %0, %1;" : "=r"(r) : "f"(x));
    return r;
}
__device__ __forceinline__ float f2tf_f(float x) {
    return __uint_as_float(f2tf(x));
}
__device__ __forceinline__ float ex2(float x) {
    float y;
    asm("ex2.approx.f32 %0, %1;" : "=f"(y) : "f"(x));
    return y;
}

__device__ __forceinline__ void mma_tf32(float* c, const unsigned* a, const unsigned* b) {
    asm volatile(
        "mma.sync.aligned.m16n8k8.row.col.f32.tf32.tf32.f32 "
        "{%0,%1,%2,%3}, {%4,%5,%6,%7}, {%8,%9}, {%0,%1,%2,%3};"
        : "+f"(c[0]), "+f"(c[1]), "+f"(c[2]), "+f"(c[3])
        : "r"(a[0]), "r"(a[1]), "r"(a[2]), "r"(a[3]),
          "r"(b[0]), "r"(b[1]));
}

__device__ __forceinline__ void ldsm4(unsigned* r, unsigned addr) {
    asm volatile("ldmatrix.sync.aligned.m8n8.x4.shared.b16 {%0,%1,%2,%3}, [%4];"
        : "=r"(r[0]), "=r"(r[1]), "=r"(r[2]), "=r"(r[3]) : "r"(addr));
}

// cp.async helpers
__device__ __forceinline__ void cpasync16(void* smem_dst, const void* gsrc) {
    unsigned s = (unsigned)__cvta_generic_to_shared(smem_dst);
    asm volatile("cp.async.cg.shared.global [%0], [%1], 16;\n" :: "r"(s), "l"(gsrc));
}
__device__ __forceinline__ void cpasync_commit() {
    asm volatile("cp.async.commit_group;\n");
}
template <int N>
__device__ __forceinline__ void cpasync_wait() {
    asm volatile("cp.async.wait_group %0;\n" :: "n"(N));
}

// ---------------------------------------------------------------------------
// Pre-round fp32 -> tf32 bits (elementwise, float4 grid-stride) — for x
// ---------------------------------------------------------------------------
__global__ void cvt_tf32_kernel(const float4* __restrict__ in,
                                float4* __restrict__ out, int n4)
{
    for (int i = blockIdx.x * blockDim.x + threadIdx.x; i < n4;
         i += gridDim.x * blockDim.x) {
        float4 v = in[i];
        v.x = f2tf_f(v.x); v.y = f2tf_f(v.y); v.z = f2tf_f(v.z); v.w = f2tf_f(v.w);
        out[i] = v;
    }
}

// ---------------------------------------------------------------------------
// Transpose + pre-round: out[n][k] = tf32(in[k][n]).  in: [K][N]
// ---------------------------------------------------------------------------
__global__ void cvt_t_kernel(const float* __restrict__ in,
                             float* __restrict__ out, int K, int N)
{
    __shared__ float tile[32][33];
    const int k0 = blockIdx.y * 32;
    const int n0 = blockIdx.x * 32;
#pragma unroll
    for (int i = threadIdx.y; i < 32; i += 8)
        tile[i][threadIdx.x] = in[(size_t)(k0 + i) * N + n0 + threadIdx.x];
    __syncthreads();
#pragma unroll
    for (int i = threadIdx.y; i < 32; i += 8)
        out[(size_t)(n0 + i) * K + k0 + threadIdx.x] = f2tf_f(tile[threadIdx.x][i]);
}

// ---------------------------------------------------------------------------
// TF32 GEMM, B pre-transposed.  C = A[M,K] @ B'[N,K]^T
// 128x128 tile, BK=32, cp.async 3-stage, 2 CTAs/SM, ldmatrix fragment loads.
// Pipeline fix (R13): stage-(ks+2) loads issued BEFORE compute (stage is free
// at the sync), so loads overlap the full compute phase -> true 3-deep.
// MODE 0: A=g_x, B=g_wa, epilogue scatters into g_q/g_k/g_vt (V transposed!)
// MODE 1: A=g_y, B=g_wp, epilogue writes row-major C (d_out)
// ---------------------------------------------------------------------------
#define ASTR 36
#define STAGES 3
#define GEMM_SMEM (STAGES * 128 * ASTR * 2 * 4)   // 110,592 B

template <int MODE>
__global__ void __launch_bounds__(256, 2)
gemm_tf32(float* __restrict__ Cp, int M, int N, int K)
{
    extern __shared__ unsigned gsm[];
    unsigned* As = gsm;                         // [STAGES][128][ASTR]
    unsigned* Bs = gsm + STAGES * 128 * ASTR;   // [STAGES][128][ASTR]

    const float* A = (MODE == 0) ? g_x : g_y;
    const float* B = (MODE == 0) ? g_wa : g_wp;   // [N][K]

    const int bx = blockIdx.x;
    const int by = blockIdx.y;
    const int tid  = threadIdx.x;
    const int lane = tid & 31;
    const int warp = tid >> 5;
    const int wm = warp >> 1;
    const int wn = warp & 1;
    const int tig = lane & 3;
    const int grp = lane >> 2;

    const int l_row = tid >> 3;          // 0..31
    const int l_kc  = (tid & 7) * 4;     // 0..28

    const float* Abase = A + (size_t)(by * 128) * K;
    const float* Bbase = B + (size_t)(bx * 128) * K;

    const int g8 = lane >> 3;
    const int r8 = lane & 7;
    const int a_ro = (g8 & 1) * 8 + r8;
    const int a_co = (g8 >> 1) * 4;
    const int b_ro = (g8 >> 1) * 8 + r8;
    const int b_co = (g8 & 1) * 4;

    const unsigned asb = (unsigned)__cvta_generic_to_shared(As);
    const unsigned bsb = (unsigned)__cvta_generic_to_shared(Bs);

    float acc[2][8][4];
#pragma unroll
    for (int i = 0; i < 2; i++)
#pragma unroll
        for (int j = 0; j < 8; j++)
#pragma unroll
            for (int r = 0; r < 4; r++) acc[i][j][r] = 0.f;

    const int nk = K >> 5;   // K/32

#pragma unroll
    for (int p = 0; p < STAGES - 1; p++) {
        const int k0 = p << 5;
#pragma unroll
        for (int rr = 0; rr < 4; rr++) {
            const int r = l_row + rr * 32;
            cpasync16(&As[((size_t)p * 128 + r) * ASTR + l_kc],
                      Abase + (size_t)r * K + k0 + l_kc);
            cpasync16(&Bs[((size_t)p * 128 + r) * ASTR + l_kc],
                      Bbase + (size_t)r * K + k0 + l_kc);
        }
        cpasync_commit();
    }

    for (int ks = 0; ks < nk; ks++) {
        const int s = ks % STAGES;
        cpasync_wait<STAGES - 2>();
        __syncthreads();

        // issue loads for stage ks+2 BEFORE compute: stage (ks+2)%3 ==
        // (ks-1)%3 was fully consumed last iteration (proven by the sync).
        if (ks + STAGES - 1 < nk) {
            const int so = (ks + STAGES - 1) % STAGES;
            const int k0 = (ks + STAGES - 1) << 5;
#pragma unroll
            for (int rr = 0; rr < 4; rr++) {
                const int r = l_row + rr * 32;
                cpasync16(&As[((size_t)so * 128 + r) * ASTR + l_kc],
                          Abase + (size_t)r * K + k0 + l_kc);
                cpasync16(&Bs[((size_t)so * 128 + r) * ASTR + l_kc],
                          Bbase + (size_t)r * K + k0 + l_kc);
            }
        }
        cpasync_commit();

#pragma unroll
        for (int kk = 0; kk < 4; kk++) {
            const int kb = kk * 8;
            unsigned af[2][4], bf[8][2];
#pragma unroll
            for (int mt = 0; mt < 2; mt++) {
                unsigned addr = asb +
                    ((s*128 + wm*32 + mt*16 + a_ro) * ASTR + kb + a_co) * 4;
                ldsm4(af[mt], addr);
            }
#pragma unroll
            for (int ntp = 0; ntp < 4; ntp++) {
                unsigned bq[4];
                unsigned addr = bsb +
                    ((s*128 + wn*64 + ntp*16 + b_ro) * ASTR + kb + b_co) * 4;
                ldsm4(bq, addr);
                bf[2*ntp][0]   = bq[0]; bf[2*ntp][1]   = bq[1];
                bf[2*ntp+1][0] = bq[2]; bf[2*ntp+1][1] = bq[3];
            }
#pragma unroll
            for (int mt = 0; mt < 2; mt++)
#pragma unroll
                for (int nt = 0; nt < 8; nt++)
                    mma_tf32(acc[mt][nt], af[mt], bf[nt]);
        }
    }

    // epilogue
#pragma unroll
    for (int mt = 0; mt < 2; mt++) {
        const int row0 = by * 128 + wm * 32 + mt * 16 + grp;
#pragma unroll
        for (int nt = 0; nt < 8; nt++) {
            const int col = bx * 128 + wn * 64 + nt * 8 + tig * 2;
            if (MODE == 0) {
#pragma unroll
                for (int half = 0; half < 2; half++) {
                    const int row = row0 + half * 8;
                    const int bb = row >> 11;
                    const int t  = row & 2047;
                    const int which = col >> 11;
                    const int c = col & 2047;
                    const int h = c >> 7;
                    const int dd = c & 127;
                    float v0 = acc[mt][nt][half * 2];
                    float v1 = acc[mt][nt][half * 2 + 1];
                    if (which == 2) {
                        // V transposed: g_vt[(bh*HD + dd)*TT + t]
                        float* dst = g_vt + ((size_t)((bb*NH + h)*HD + dd))*TT + t;
                        dst[0]  = f2tf_f(v0);
                        dst[TT] = f2tf_f(v1);
                    } else {
                        float* base = (which == 0) ? g_q : g_k;
                        float* dst = base + ((size_t)(bb*NH + h)*TT + t)*HD + dd;
                        *(float2*)dst = make_float2(v0, v1);
                    }
                }
            } else {
                *(float2*)(Cp + (size_t)row0 * N + col) =
                    make_float2(acc[mt][nt][0], acc[mt][nt][1]);
                *(float2*)(Cp + (size_t)(row0 + 8) * N + col) =
                    make_float2(acc[mt][nt][2], acc[mt][nt][3]);
            }
        }
    }
}

// ---------------------------------------------------------------------------
// RoPE: rotate q,k in place, pre-round to tf32.
// q additionally scaled by (1/sqrt(hd))*log2(e) for log2-domain softmax.
// ---------------------------------------------------------------------------
#define QSCALE (0.08838834764831845f * 1.4426950408889634f)

__global__ void rope_kernel(const float* __restrict__ cosp,
                            const float* __restrict__ sinp)
{
    int row = blockIdx.x;
    int t = row & (TT - 1);
    int tid = threadIdx.x;
    int d = tid & 63;
    bool isq = (tid < 64);
    float* arr = isq ? g_q : g_k;
    float sc = isq ? QSCALE : 1.f;
    float* base = arr + (size_t)row * HD;
    float c = cosp[t*64 + d];
    float s = sinp[t*64 + d];
    float x1 = base[d];
    float x2 = base[d + 64];
    base[d]      = f2tf_f((x1*c - x2*s) * sc);
    base[d + 64] = f2tf_f((x1*s + x2*c) * sc);
}

// ---------------------------------------------------------------------------
// Flash attention v4: Q fragments in registers; K + V^T double-buffered
// cp.async; K AND V fragments via ldmatrix; log2-domain ex2 softmax.
// Br=128 (8 warps x 16 rows), Bc=64.  LPT CTA order (neutral, kept).
// ---------------------------------------------------------------------------
#define FBR 128
#define FBC 64
#define FKS 132                       // K tile row stride (words), 64 rows
#define VTS 68                        // V^T tile row stride (words), 128 rows
#define FPS 68
#define STW (FBC*FKS + HD*VTS)        // words per stage: K + V^T = 17152
#define FLASH4_SMEM ((2*STW + 8*16*FPS) * 4)   // 172,032 B

__global__ void __launch_bounds__(256)
flash4_kernel()
{
    extern __shared__ unsigned sm[];
    unsigned* uP = sm + 2*STW;

    const int qt  = gridDim.x - 1 - blockIdx.x;   // LPT: heavy tiles first
    const int bh  = blockIdx.y;
    const int tid = threadIdx.x;
    const int lane = tid & 31;
    const int wq   = tid >> 5;
    const int tig  = lane & 3;
    const int grp  = lane >> 2;
    const int g8 = lane >> 3;
    const int r8 = lane & 7;
    const int b_ro = (g8 >> 1) * 8 + r8;
    const int b_co = (g8 & 1) * 4;

    const unsigned smb = (unsigned)__cvta_generic_to_shared(sm);

    // ---- Q fragments straight from gmem into registers (tf32 bits) ----
    unsigned qf[16][4];
    {
        const unsigned* Qg = (const unsigned*)g_q + ((size_t)bh*TT + qt*FBR)*HD;
        const int r0 = (wq*16 + grp) * HD;
        const int r1 = (wq*16 + grp + 8) * HD;
#pragma unroll
        for (int ks = 0; ks < 16; ks++) {
            const int d0 = ks * 8;
            qf[ks][0] = Qg[r0 + d0 + tig];
            qf[ks][1] = Qg[r1 + d0 + tig];
            qf[ks][2] = Qg[r0 + d0 + tig + 4];
            qf[ks][3] = Qg[r1 + d0 + tig + 4];
        }
    }

    float m_i[2], l_i[2];
    m_i[0] = m_i[1] = -1e30f;
    l_i[0] = l_i[1] = 0.f;
    float oc[16][4];
#pragma unroll
    for (int n = 0; n < 16; n++)
#pragma unroll
        for (int r = 0; r < 4; r++) oc[n][r] = 0.f;

    const int warp_row0 = qt*FBR + wq*16;
    const int nblocks = 2*qt + 2;

    const float* Kall  = g_k  + (size_t)bh*TT*HD;
    const float* Vtall = g_vt + (size_t)bh*HD*TT;

    // stage loader: K tile [64 tok][128 hd], V^T tile [128 hd][64 tok]
#define ISSUE_KV(JC, ST)                                                       \
    {                                                                          \
        const float* Kg  = Kall  + (size_t)(JC)*FBC*HD;                        \
        const float* Vtg = Vtall + (JC)*FBC;                                   \
        unsigned* dK = sm + (ST)*STW;                                          \
        unsigned* dV = dK + FBC*FKS;                                           \
        _Pragma("unroll")                                                      \
        for (int i = 0; i < 8; i++) {                                          \
            int lin = tid + i*256;                                             \
            int r  = lin >> 5;                                                 \
            int c4 = (lin & 31) * 4;                                           \
            cpasync16(&dK[r*FKS + c4], Kg + (size_t)r*HD + c4);                \
        }                                                                      \
        _Pragma("unroll")                                                      \
        for (int i = 0; i < 8; i++) {                                          \
            int lin = tid + i*256;                                             \
            int r  = lin >> 4;            /* 0..127 hd row */                  \
            int c4 = (lin & 15) * 4;      /* 0..60 token col */                \
            cpasync16(&dV[r*VTS + c4], Vtg + (size_t)r*TT + c4);               \
        }                                                                      \
    }

    ISSUE_KV(0, 0);
    cpasync_commit();

    for (int jc = 0; jc < nblocks; jc++) {
        const int s = jc & 1;
        cpasync_wait<0>();
        __syncthreads();
        if (jc + 1 < nblocks) {
            ISSUE_KV(jc + 1, s ^ 1);
            cpasync_commit();
        }

        if (jc*FBC > warp_row0 + 15) continue;
        const bool diag = (jc*FBC + FBC - 1) > warp_row0;

        const unsigned kbase = smb + (unsigned)(s*STW) * 4;
        const unsigned vbase = smb + (unsigned)(s*STW + FBC*FKS) * 4;

        // ---- S = Q K^T (log2 units) ----
        float sc[8][4];
#pragma unroll
        for (int n = 0; n < 8; n++)
#pragma unroll
            for (int r = 0; r < 4; r++) sc[n][r] = 0.f;

#pragma unroll
        for (int ks = 0; ks < 16; ks++) {
            const int d0 = ks*8;
            unsigned bf[8][2];
#pragma unroll
            for (int ntp = 0; ntp < 4; ntp++) {
                unsigned bq[4];
                unsigned addr = kbase + ((ntp*16 + b_ro)*FKS + d0 + b_co) * 4;
                ldsm4(bq, addr);
                bf[2*ntp][0]   = bq[0]; bf[2*ntp][1]   = bq[1];
                bf[2*ntp+1][0] = bq[2]; bf[2*ntp+1][1] = bq[3];
            }
#pragma unroll
            for (int nt = 0; nt < 8; nt++)
                mma_tf32(sc[nt], qf[ks], bf[nt]);
        }

        // ---- online softmax (log2 domain) ----
        unsigned* Pw = uP + wq*16*FPS;
#pragma unroll
        for (int h = 0; h < 2; h++) {
            const int row = warp_row0 + grp + h*8;
            float rmax = -1e30f;
            if (diag) {
#pragma unroll
                for (int nt = 0; nt < 8; nt++)
#pragma unroll
                    for (int c = 0; c < 2; c++) {
                        const int col = jc*FBC + nt*8 + tig*2 + c;
                        float v = sc[nt][h*2 + c];
                        if (col > row) v = -1e30f;
                        sc[nt][h*2 + c] = v;
                        rmax = fmaxf(rmax, v);
                    }
            } else {
#pragma unroll
                for (int nt = 0; nt < 8; nt++)
                    rmax = fmaxf(rmax, fmaxf(sc[nt][h*2], sc[nt][h*2 + 1]));
            }
            rmax = fmaxf(rmax, __shfl_xor_sync(0xffffffffu, rmax, 1));
            rmax = fmaxf(rmax, __shfl_xor_sync(0xffffffffu, rmax, 2));

            const float m_new = fmaxf(m_i[h], rmax);
            const float fac = ex2(m_i[h] - m_new);
            float rsum = 0.f;
#pragma unroll
            for (int nt = 0; nt < 8; nt++) {
#pragma unroll
                for (int c = 0; c < 2; c++) {
                    float p = ex2(sc[nt][h*2 + c] - m_new);
                    rsum += p;
                    Pw[(grp + h*8)*FPS + nt*8 + tig*2 + c] = f2tf(p);
                }
            }
            rsum += __shfl_xor_sync(0xffffffffu, rsum, 1);
            rsum += __shfl_xor_sync(0xffffffffu, rsum, 2);

            l_i[h] = l_i[h]*fac + rsum;
            m_i[h] = m_new;
#pragma unroll
            for (int nt = 0; nt < 16; nt++) {
                oc[nt][h*2]     *= fac;
                oc[nt][h*2 + 1] *= fac;
            }
        }
        __syncwarp();

        // ---- O += P V  (V fragments via ldmatrix on V^T) ----
#pragma unroll
        for (int k0 = 0; k0 < FBC; k0 += 8) {
            unsigned af[4];
            af[0] = Pw[(grp    )*FPS + k0 + tig];
            af[1] = Pw[(grp + 8)*FPS + k0 + tig];
            af[2] = Pw[(grp    )*FPS + k0 + tig + 4];
            af[3] = Pw[(grp + 8)*FPS + k0 + tig + 4];
#pragma unroll
            for (int np = 0; np < 8; np++) {
                unsigned bq[4];
                unsigned addr = vbase + ((np*16 + b_ro)*VTS + k0 + b_co) * 4;
                ldsm4(bq, addr);
                unsigned bf0[2] = {bq[0], bq[1]};
                unsigned bf1[2] = {bq[2], bq[3]};
                mma_tf32(oc[2*np],     af, bf0);
                mma_tf32(oc[2*np + 1], af, bf1);
            }
        }
    }

    // epilogue: y pre-rounded for gemm<1>
    const int b = bh >> 4;
    const int h = bh & 15;
#pragma unroll
    for (int hh = 0; hh < 2; hh++) {
        const int t = qt*FBR + wq*16 + grp + hh*8;
        const float inv = 1.f / l_i[hh];
        float* yrow = g_y + ((size_t)(b*TT + t))*CC + h*HD;
#pragma unroll
        for (int nt = 0; nt < 16; nt++) {
            *(float2*)(yrow + nt*8 + tig*2) =
                make_float2(f2tf_f(oc[nt][hh*2] * inv),
                            f2tf_f(oc[nt][hh*2 + 1] * inv));
        }
    }
}

// ---------------------------------------------------------------------------
// launch
// ---------------------------------------------------------------------------
extern "C" void kernel_launch(void* const* d_in, const int* in_sizes, int n_in,
                              void* d_out, int out_size)
{
    const float* x    = (const float*)d_in[0];
    const float* cosp = (const float*)d_in[1];
    const float* sinp = (const float*)d_in[2];
    const float* Wa   = (const float*)d_in[3];
    const float* Wp   = (const float*)d_in[4];
    float* out = (float*)d_out;

    float *dx, *dwa, *dwp;
    cudaGetSymbolAddress((void**)&dx,  g_x);
    cudaGetSymbolAddress((void**)&dwa, g_wa);
    cudaGetSymbolAddress((void**)&dwp, g_wp);

    // 0) pre-round x; transpose + pre-round weights
    cvt_tf32_kernel<<<2048, 256>>>((const float4*)x, (float4*)dx, MM*CC/4);
    cvt_t_kernel<<<dim3(N_QKV/32, CC/32), dim3(32, 8)>>>(Wa, dwa, CC, N_QKV);
    cvt_t_kernel<<<dim3(CC/32,   CC/32), dim3(32, 8)>>>(Wp, dwp, CC, CC);

    // 1) qkv = x @ W_attn -> head-major q/k + transposed v
    cudaFuncSetAttribute(gemm_tf32<0>, cudaFuncAttributeMaxDynamicSharedMemorySize,
                         GEMM_SMEM);
    gemm_tf32<0><<<dim3(N_QKV/128, MM/128), 256, GEMM_SMEM>>>(nullptr, MM, N_QKV, CC);

    // 2) RoPE on q,k
    rope_kernel<<<BB*NH*TT, 128>>>(cosp, sinp);

    // 3) flash attention -> g_y
    cudaFuncSetAttribute(flash4_kernel, cudaFuncAttributeMaxDynamicSharedMemorySize,
                         FLASH4_SMEM);
    flash4_kernel<<<dim3(TT/FBR, BB*NH), 256, FLASH4_SMEM>>>();

    // 4) out = y @ W_proj
    cudaFuncSetAttribute(gemm_tf32<1>, cudaFuncAttributeMaxDynamicSharedMemorySize,
                         GEMM_SMEM);
    gemm_tf32<1><<<dim3(CC/128, MM/128), 256, GEMM_SMEM>>>(out, MM, CC, CC);
}

// round 15
// speedup vs baseline: 1.0807x; 1.0807x over previous
#include <cuda_runtime.h>
#include <cuda_bf16.h>
#include <math.h>

// Problem constants
#define BB   2
#define TT   2048
#define CC   2048
#define NH   16
#define HD   128
#define MM   (BB*TT)        // 4096
#define N_QKV (3*CC)        // 6144

// ---------------------------------------------------------------------------
// Scratch (device globals; no runtime allocation)
// ---------------------------------------------------------------------------
__device__ float g_q[(size_t)BB*NH*TT*HD];   // [B,H,T,hd], q pre-scaled, tf32 bits
__device__ float g_k[(size_t)BB*NH*TT*HD];   // [B,H,T,hd], tf32 bits
__device__ float g_vt[(size_t)BB*NH*HD*TT];  // [B,H,hd,T]  V TRANSPOSED, tf32 bits
__device__ float g_y[(size_t)BB*TT*CC];      // tf32 bits
__device__ float g_x[(size_t)MM*CC];         // tf32 bits
__device__ float g_wa[(size_t)CC*N_QKV];     // tf32 bits, W_attn^T [N_QKV][CC]
__device__ float g_wp[(size_t)CC*CC];        // tf32 bits, W_proj^T [CC][CC]

// q scale folded with log2(e) for log2-domain softmax
#define QSCALE (0.08838834764831845f * 1.4426950408889634f)

// ---------------------------------------------------------------------------
// TF32 / math helpers
// ---------------------------------------------------------------------------
__device__ __forceinline__ unsigned f2tf(float x) {
    unsigned r;
    asm("cvt.rna.tf32.f32 %0, %1;" : "=r"(r) : "f"(x));
    return r;
}
__device__ __forceinline__ float f2tf_f(float x) {
    return __uint_as_float(f2tf(x));
}
__device__ __forceinline__ float ex2(float x) {
    float y;
    asm("ex2.approx.f32 %0, %1;" : "=f"(y) : "f"(x));
    return y;
}

__device__ __forceinline__ void mma_tf32(float* c, const unsigned* a, const unsigned* b) {
    asm volatile(
        "mma.sync.aligned.m16n8k8.row.col.f32.tf32.tf32.f32 "
        "{%0,%1,%2,%3}, {%4,%5,%6,%7}, {%8,%9}, {%0,%1,%2,%3};"
        : "+f"(c[0]), "+f"(c[1]), "+f"(c[2]), "+f"(c[3])
        : "r"(a[0]), "r"(a[1]), "r"(a[2]), "r"(a[3]),
          "r"(b[0]), "r"(b[1]));
}

__device__ __forceinline__ void ldsm4(unsigned* r, unsigned addr) {
    asm volatile("ldmatrix.sync.aligned.m8n8.x4.shared.b16 {%0,%1,%2,%3}, [%4];"
        : "=r"(r[0]), "=r"(r[1]), "=r"(r[2]), "=r"(r[3]) : "r"(addr));
}

// cp.async helpers
__device__ __forceinline__ void cpasync16(void* smem_dst, const void* gsrc) {
    unsigned s = (unsigned)__cvta_generic_to_shared(smem_dst);
    asm volatile("cp.async.cg.shared.global [%0], [%1], 16;\n" :: "r"(s), "l"(gsrc));
}
__device__ __forceinline__ void cpasync_commit() {
    asm volatile("cp.async.commit_group;\n");
}
template <int N>
__device__ __forceinline__ void cpasync_wait() {
    asm volatile("cp.async.wait_group %0;\n" :: "n"(N));
}

// ---------------------------------------------------------------------------
// Pre-round fp32 -> tf32 bits (elementwise, float4 grid-stride) — for x
// ---------------------------------------------------------------------------
__global__ void cvt_tf32_kernel(const float4* __restrict__ in,
                                float4* __restrict__ out, int n4)
{
    for (int i = blockIdx.x * blockDim.x + threadIdx.x; i < n4;
         i += gridDim.x * blockDim.x) {
        float4 v = in[i];
        v.x = f2tf_f(v.x); v.y = f2tf_f(v.y); v.z = f2tf_f(v.z); v.w = f2tf_f(v.w);
        out[i] = v;
    }
}

// ---------------------------------------------------------------------------
// Transpose + pre-round: out[n][k] = tf32(in[k][n]).  in: [K][N]
// ---------------------------------------------------------------------------
__global__ void cvt_t_kernel(const float* __restrict__ in,
                             float* __restrict__ out, int K, int N)
{
    __shared__ float tile[32][33];
    const int k0 = blockIdx.y * 32;
    const int n0 = blockIdx.x * 32;
#pragma unroll
    for (int i = threadIdx.y; i < 32; i += 8)
        tile[i][threadIdx.x] = in[(size_t)(k0 + i) * N + n0 + threadIdx.x];
    __syncthreads();
#pragma unroll
    for (int i = threadIdx.y; i < 32; i += 8)
        out[(size_t)(n0 + i) * K + k0 + threadIdx.x] = f2tf_f(tile[threadIdx.x][i]);
}

// ---------------------------------------------------------------------------
// TF32 GEMM, B pre-transposed.  C = A[M,K] @ B'[N,K]^T
// 128x128 tile, BK=32, cp.async 3-stage (R10 order: issue AFTER compute),
// 2 CTAs/SM, ldmatrix fragment loads.
// MODE 0: A=g_x, B=g_wa; epilogue applies RoPE(+scale) to q/k in-register via
//         smem exchange (col tile == one head), scatters q/k/vt.
// MODE 1: A=g_y, B=g_wp, epilogue writes row-major C (d_out)
// ---------------------------------------------------------------------------
#define ASTR 36
#define STAGES 3
#define GEMM_SMEM (STAGES * 128 * ASTR * 2 * 4)   // 110,592 B

template <int MODE>
__global__ void __launch_bounds__(256, 2)
gemm_tf32(float* __restrict__ Cp,
          const float* __restrict__ cosp, const float* __restrict__ sinp,
          int M, int N, int K)
{
    extern __shared__ unsigned gsm[];
    unsigned* As = gsm;                         // [STAGES][128][ASTR]
    unsigned* Bs = gsm + STAGES * 128 * ASTR;   // [STAGES][128][ASTR]

    const float* A = (MODE == 0) ? g_x : g_y;
    const float* B = (MODE == 0) ? g_wa : g_wp;   // [N][K]

    const int bx = blockIdx.x;
    const int by = blockIdx.y;
    const int tid  = threadIdx.x;
    const int lane = tid & 31;
    const int warp = tid >> 5;
    const int wm = warp >> 1;
    const int wn = warp & 1;
    const int tig = lane & 3;
    const int grp = lane >> 2;

    const int l_row = tid >> 3;          // 0..31
    const int l_kc  = (tid & 7) * 4;     // 0..28

    const float* Abase = A + (size_t)(by * 128) * K;
    const float* Bbase = B + (size_t)(bx * 128) * K;

    const int g8 = lane >> 3;
    const int r8 = lane & 7;
    const int a_ro = (g8 & 1) * 8 + r8;
    const int a_co = (g8 >> 1) * 4;
    const int b_ro = (g8 >> 1) * 8 + r8;
    const int b_co = (g8 & 1) * 4;

    const unsigned asb = (unsigned)__cvta_generic_to_shared(As);
    const unsigned bsb = (unsigned)__cvta_generic_to_shared(Bs);

    float acc[2][8][4];
#pragma unroll
    for (int i = 0; i < 2; i++)
#pragma unroll
        for (int j = 0; j < 8; j++)
#pragma unroll
            for (int r = 0; r < 4; r++) acc[i][j][r] = 0.f;

    const int nk = K >> 5;   // K/32

#pragma unroll
    for (int p = 0; p < STAGES - 1; p++) {
        const int k0 = p << 5;
#pragma unroll
        for (int rr = 0; rr < 4; rr++) {
            const int r = l_row + rr * 32;
            cpasync16(&As[((size_t)p * 128 + r) * ASTR + l_kc],
                      Abase + (size_t)r * K + k0 + l_kc);
            cpasync16(&Bs[((size_t)p * 128 + r) * ASTR + l_kc],
                      Bbase + (size_t)r * K + k0 + l_kc);
        }
        cpasync_commit();
    }

    for (int ks = 0; ks < nk; ks++) {
        const int s = ks % STAGES;
        cpasync_wait<STAGES - 2>();
        __syncthreads();

#pragma unroll
        for (int kk = 0; kk < 4; kk++) {
            const int kb = kk * 8;
            unsigned af[2][4], bf[8][2];
#pragma unroll
            for (int mt = 0; mt < 2; mt++) {
                unsigned addr = asb +
                    ((s*128 + wm*32 + mt*16 + a_ro) * ASTR + kb + a_co) * 4;
                ldsm4(af[mt], addr);
            }
#pragma unroll
            for (int ntp = 0; ntp < 4; ntp++) {
                unsigned bq[4];
                unsigned addr = bsb +
                    ((s*128 + wn*64 + ntp*16 + b_ro) * ASTR + kb + b_co) * 4;
                ldsm4(bq, addr);
                bf[2*ntp][0]   = bq[0]; bf[2*ntp][1]   = bq[1];
                bf[2*ntp+1][0] = bq[2]; bf[2*ntp+1][1] = bq[3];
            }
#pragma unroll
            for (int mt = 0; mt < 2; mt++)
#pragma unroll
                for (int nt = 0; nt < 8; nt++)
                    mma_tf32(acc[mt][nt], af[mt], bf[nt]);
        }

        // R10 order: issue loads for stage ks+2 AFTER compute
        if (ks + STAGES - 1 < nk) {
            const int so = (ks + STAGES - 1) % STAGES;
            const int k0 = (ks + STAGES - 1) << 5;
#pragma unroll
            for (int rr = 0; rr < 4; rr++) {
                const int r = l_row + rr * 32;
                cpasync16(&As[((size_t)so * 128 + r) * ASTR + l_kc],
                          Abase + (size_t)r * K + k0 + l_kc);
                cpasync16(&Bs[((size_t)so * 128 + r) * ASTR + l_kc],
                          Bbase + (size_t)r * K + k0 + l_kc);
            }
        }
        cpasync_commit();
    }

    // ---------------- epilogue ----------------
    if (MODE == 0) {
        const int which = bx >> 4;        // 0=q, 1=k, 2=v (whole CTA uniform)
        if (which == 2) {
            // V: pre-round + transposed scatter (unchanged)
#pragma unroll
            for (int mt = 0; mt < 2; mt++) {
#pragma unroll
                for (int nt = 0; nt < 8; nt++) {
                    const int col = bx * 128 + wn * 64 + nt * 8 + tig * 2;
                    const int h  = (col & 2047) >> 7;
                    const int dd = col & 127;
#pragma unroll
                    for (int half = 0; half < 2; half++) {
                        const int row = by*128 + wm*32 + mt*16 + grp + half*8;
                        const int bb = row >> 11;
                        const int t  = row & 2047;
                        float* dst = g_vt + ((size_t)((bb*NH + h)*HD + dd))*TT + t;
                        dst[0]  = f2tf_f(acc[mt][nt][half*2]);
                        dst[TT] = f2tf_f(acc[mt][nt][half*2 + 1]);
                    }
                }
            }
        } else {
            // q/k: fused RoPE.  Column tile == one full head (h = bx & 15).
            // Exchange partner values (d <-> d+64) through smem (pipeline
            // buffers are dead now).
            float* ex = (float*)gsm;              // [128][132]
            __syncthreads();                      // mainloop smem fully done
#pragma unroll
            for (int mt = 0; mt < 2; mt++)
#pragma unroll
                for (int nt = 0; nt < 8; nt++)
#pragma unroll
                    for (int half = 0; half < 2; half++) {
                        const int rl = wm*32 + mt*16 + grp + half*8;
                        const int cl = wn*64 + nt*8 + tig*2;
                        ex[rl*132 + cl]     = acc[mt][nt][half*2];
                        ex[rl*132 + cl + 1] = acc[mt][nt][half*2 + 1];
                    }
            __syncthreads();

            const int h = bx & 15;
            const float qs = (which == 0) ? QSCALE : 1.f;
            float* base = (which == 0) ? g_q : g_k;
#pragma unroll
            for (int mt = 0; mt < 2; mt++) {
#pragma unroll
                for (int nt = 0; nt < 8; nt++) {
                    const int cl = wn*64 + nt*8 + tig*2;
                    const int d6 = cl & 63;
#pragma unroll
                    for (int half = 0; half < 2; half++) {
                        const int rl = wm*32 + mt*16 + grp + half*8;
                        const int row = by*128 + rl;
                        const int bb = row >> 11;
                        const int t  = row & 2047;
                        const float x0 = acc[mt][nt][half*2];
                        const float x1 = acc[mt][nt][half*2 + 1];
                        const float p0 = ex[rl*132 + (cl ^ 64)];
                        const float p1 = ex[rl*132 + ((cl + 1) ^ 64)];
                        const float2 cc = *(const float2*)(cosp + t*64 + d6);
                        const float2 ss = *(const float2*)(sinp + t*64 + d6);
                        float o0, o1;
                        if (wn == 0) {            // d < 64: x1*c - x2*s
                            o0 = x0*cc.x - p0*ss.x;
                            o1 = x1*cc.y - p1*ss.y;
                        } else {                  // d >= 64: x1*s + x2*c
                            o0 = p0*ss.x + x0*cc.x;
                            o1 = p1*ss.y + x1*cc.y;
                        }
                        float* dst = base + ((size_t)(bb*NH + h)*TT + t)*HD + cl;
                        *(float2*)dst = make_float2(f2tf_f(o0*qs), f2tf_f(o1*qs));
                    }
                }
            }
        }
    } else {
#pragma unroll
        for (int mt = 0; mt < 2; mt++) {
            const int row0 = by * 128 + wm * 32 + mt * 16 + grp;
#pragma unroll
            for (int nt = 0; nt < 8; nt++) {
                const int col = bx * 128 + wn * 64 + nt * 8 + tig * 2;
                *(float2*)(Cp + (size_t)row0 * N + col) =
                    make_float2(acc[mt][nt][0], acc[mt][nt][1]);
                *(float2*)(Cp + (size_t)(row0 + 8) * N + col) =
                    make_float2(acc[mt][nt][2], acc[mt][nt][3]);
            }
        }
    }
}

// ---------------------------------------------------------------------------
// Flash attention v4: Q fragments in registers; K + V^T double-buffered
// cp.async; K AND V fragments via ldmatrix; log2-domain ex2 softmax.
// Br=128 (8 warps x 16 rows), Bc=64.  LPT CTA order.
// ---------------------------------------------------------------------------
#define FBR 128
#define FBC 64
#define FKS 132                       // K tile row stride (words), 64 rows
#define VTS 68                        // V^T tile row stride (words), 128 rows
#define FPS 68
#define STW (FBC*FKS + HD*VTS)        // words per stage: K + V^T = 17152
#define FLASH4_SMEM ((2*STW + 8*16*FPS) * 4)   // 172,032 B

__global__ void __launch_bounds__(256)
flash4_kernel()
{
    extern __shared__ unsigned sm[];
    unsigned* uP = sm + 2*STW;

    const int qt  = gridDim.x - 1 - blockIdx.x;   // LPT: heavy tiles first
    const int bh  = blockIdx.y;
    const int tid = threadIdx.x;
    const int lane = tid & 31;
    const int wq   = tid >> 5;
    const int tig  = lane & 3;
    const int grp  = lane >> 2;
    const int g8 = lane >> 3;
    const int r8 = lane & 7;
    const int b_ro = (g8 >> 1) * 8 + r8;
    const int b_co = (g8 & 1) * 4;

    const unsigned smb = (unsigned)__cvta_generic_to_shared(sm);

    // ---- Q fragments straight from gmem into registers (tf32 bits) ----
    unsigned qf[16][4];
    {
        const unsigned* Qg = (const unsigned*)g_q + ((size_t)bh*TT + qt*FBR)*HD;
        const int r0 = (wq*16 + grp) * HD;
        const int r1 = (wq*16 + grp + 8) * HD;
#pragma unroll
        for (int ks = 0; ks < 16; ks++) {
            const int d0 = ks * 8;
            qf[ks][0] = Qg[r0 + d0 + tig];
            qf[ks][1] = Qg[r1 + d0 + tig];
            qf[ks][2] = Qg[r0 + d0 + tig + 4];
            qf[ks][3] = Qg[r1 + d0 + tig + 4];
        }
    }

    float m_i[2], l_i[2];
    m_i[0] = m_i[1] = -1e30f;
    l_i[0] = l_i[1] = 0.f;
    float oc[16][4];
#pragma unroll
    for (int n = 0; n < 16; n++)
#pragma unroll
        for (int r = 0; r < 4; r++) oc[n][r] = 0.f;

    const int warp_row0 = qt*FBR + wq*16;
    const int nblocks = 2*qt + 2;

    const float* Kall  = g_k  + (size_t)bh*TT*HD;
    const float* Vtall = g_vt + (size_t)bh*HD*TT;

    // stage loader: K tile [64 tok][128 hd], V^T tile [128 hd][64 tok]
#define ISSUE_KV(JC, ST)                                                       \
    {                                                                          \
        const float* Kg  = Kall  + (size_t)(JC)*FBC*HD;                        \
        const float* Vtg = Vtall + (JC)*FBC;                                   \
        unsigned* dK = sm + (ST)*STW;                                          \
        unsigned* dV = dK + FBC*FKS;                                           \
        _Pragma("unroll")                                                      \
        for (int i = 0; i < 8; i++) {                                          \
            int lin = tid + i*256;                                             \
            int r  = lin >> 5;                                                 \
            int c4 = (lin & 31) * 4;                                           \
            cpasync16(&dK[r*FKS + c4], Kg + (size_t)r*HD + c4);                \
        }                                                                      \
        _Pragma("unroll")                                                      \
        for (int i = 0; i < 8; i++) {                                          \
            int lin = tid + i*256;                                             \
            int r  = lin >> 4;            /* 0..127 hd row */                  \
            int c4 = (lin & 15) * 4;      /* 0..60 token col */                \
            cpasync16(&dV[r*VTS + c4], Vtg + (size_t)r*TT + c4);               \
        }                                                                      \
    }

    ISSUE_KV(0, 0);
    cpasync_commit();

    for (int jc = 0; jc < nblocks; jc++) {
        const int s = jc & 1;
        cpasync_wait<0>();
        __syncthreads();
        if (jc + 1 < nblocks) {
            ISSUE_KV(jc + 1, s ^ 1);
            cpasync_commit();
        }

        if (jc*FBC > warp_row0 + 15) continue;
        const bool diag = (jc*FBC + FBC - 1) > warp_row0;

        const unsigned kbase = smb + (unsigned)(s*STW) * 4;
        const unsigned vbase = smb + (unsigned)(s*STW + FBC*FKS) * 4;

        // ---- S = Q K^T (log2 units) ----
        float sc[8][4];
#pragma unroll
        for (int n = 0; n < 8; n++)
#pragma unroll
            for (int r = 0; r < 4; r++) sc[n][r] = 0.f;

#pragma unroll
        for (int ks = 0; ks < 16; ks++) {
            const int d0 = ks*8;
            unsigned bf[8][2];
#pragma unroll
            for (int ntp = 0; ntp < 4; ntp++) {
                unsigned bq[4];
                unsigned addr = kbase + ((ntp*16 + b_ro)*FKS + d0 + b_co) * 4;
                ldsm4(bq, addr);
                bf[2*ntp][0]   = bq[0]; bf[2*ntp][1]   = bq[1];
                bf[2*ntp+1][0] = bq[2]; bf[2*ntp+1][1] = bq[3];
            }
#pragma unroll
            for (int nt = 0; nt < 8; nt++)
                mma_tf32(sc[nt], qf[ks], bf[nt]);
        }

        // ---- online softmax (log2 domain) ----
        unsigned* Pw = uP + wq*16*FPS;
#pragma unroll
        for (int h = 0; h < 2; h++) {
            const int row = warp_row0 + grp + h*8;
            float rmax = -1e30f;
            if (diag) {
#pragma unroll
                for (int nt = 0; nt < 8; nt++)
#pragma unroll
                    for (int c = 0; c < 2; c++) {
                        const int col = jc*FBC + nt*8 + tig*2 + c;
                        float v = sc[nt][h*2 + c];
                        if (col > row) v = -1e30f;
                        sc[nt][h*2 + c] = v;
                        rmax = fmaxf(rmax, v);
                    }
            } else {
#pragma unroll
                for (int nt = 0; nt < 8; nt++)
                    rmax = fmaxf(rmax, fmaxf(sc[nt][h*2], sc[nt][h*2 + 1]));
            }
            rmax = fmaxf(rmax, __shfl_xor_sync(0xffffffffu, rmax, 1));
            rmax = fmaxf(rmax, __shfl_xor_sync(0xffffffffu, rmax, 2));

            const float m_new = fmaxf(m_i[h], rmax);
            const float fac = ex2(m_i[h] - m_new);
            float rsum = 0.f;
#pragma unroll
            for (int nt = 0; nt < 8; nt++) {
#pragma unroll
                for (int c = 0; c < 2; c++) {
                    float p = ex2(sc[nt][h*2 + c] - m_new);
                    rsum += p;
                    Pw[(grp + h*8)*FPS + nt*8 + tig*2 + c] = f2tf(p);
                }
            }
            rsum += __shfl_xor_sync(0xffffffffu, rsum, 1);
            rsum += __shfl_xor_sync(0xffffffffu, rsum, 2);

            l_i[h] = l_i[h]*fac + rsum;
            m_i[h] = m_new;
#pragma unroll
            for (int nt = 0; nt < 16; nt++) {
                oc[nt][h*2]     *= fac;
                oc[nt][h*2 + 1] *= fac;
            }
        }
        __syncwarp();

        // ---- O += P V  (V fragments via ldmatrix on V^T) ----
#pragma unroll
        for (int k0 = 0; k0 < FBC; k0 += 8) {
            unsigned af[4];
            af[0] = Pw[(grp    )*FPS + k0 + tig];
            af[1] = Pw[(grp + 8)*FPS + k0 + tig];
            af[2] = Pw[(grp    )*FPS + k0 + tig + 4];
            af[3] = Pw[(grp + 8)*FPS + k0 + tig + 4];
#pragma unroll
            for (int np = 0; np < 8; np++) {
                unsigned bq[4];
                unsigned addr = vbase + ((np*16 + b_ro)*VTS + k0 + b_co) * 4;
                ldsm4(bq, addr);
                unsigned bf0[2] = {bq[0], bq[1]};
                unsigned bf1[2] = {bq[2], bq[3]};
                mma_tf32(oc[2*np],     af, bf0);
                mma_tf32(oc[2*np + 1], af, bf1);
            }
        }
    }

    // epilogue: y pre-rounded for gemm<1>
    const int b = bh >> 4;
    const int h = bh & 15;
#pragma unroll
    for (int hh = 0; hh < 2; hh++) {
        const int t = qt*FBR + wq*16 + grp + hh*8;
        const float inv = 1.f / l_i[hh];
        float* yrow = g_y + ((size_t)(b*TT + t))*CC + h*HD;
#pragma unroll
        for (int nt = 0; nt < 16; nt++) {
            *(float2*)(yrow + nt*8 + tig*2) =
                make_float2(f2tf_f(oc[nt][hh*2] * inv),
                            f2tf_f(oc[nt][hh*2 + 1] * inv));
        }
    }
}

// ---------------------------------------------------------------------------
// launch
// ---------------------------------------------------------------------------
extern "C" void kernel_launch(void* const* d_in, const int* in_sizes, int n_in,
                              void* d_out, int out_size)
{
    const float* x    = (const float*)d_in[0];
    const float* cosp = (const float*)d_in[1];
    const float* sinp = (const float*)d_in[2];
    const float* Wa   = (const float*)d_in[3];
    const float* Wp   = (const float*)d_in[4];
    float* out = (float*)d_out;

    float *dx, *dwa, *dwp;
    cudaGetSymbolAddress((void**)&dx,  g_x);
    cudaGetSymbolAddress((void**)&dwa, g_wa);
    cudaGetSymbolAddress((void**)&dwp, g_wp);

    // 0) pre-round x; transpose + pre-round weights
    cvt_tf32_kernel<<<2048, 256>>>((const float4*)x, (float4*)dx, MM*CC/4);
    cvt_t_kernel<<<dim3(N_QKV/32, CC/32), dim3(32, 8)>>>(Wa, dwa, CC, N_QKV);
    cvt_t_kernel<<<dim3(CC/32,   CC/32), dim3(32, 8)>>>(Wp, dwp, CC, CC);

    // 1) qkv = x @ W_attn -> head-major q/k (RoPE fused) + transposed v
    cudaFuncSetAttribute(gemm_tf32<0>, cudaFuncAttributeMaxDynamicSharedMemorySize,
                         GEMM_SMEM);
    gemm_tf32<0><<<dim3(N_QKV/128, MM/128), 256, GEMM_SMEM>>>(
        nullptr, cosp, sinp, MM, N_QKV, CC);

    // 2) flash attention -> g_y
    cudaFuncSetAttribute(flash4_kernel, cudaFuncAttributeMaxDynamicSharedMemorySize,
                         FLASH4_SMEM);
    flash4_kernel<<<dim3(TT/FBR, BB*NH), 256, FLASH4_SMEM>>>();

    // 3) out = y @ W_proj
    cudaFuncSetAttribute(gemm_tf32<1>, cudaFuncAttributeMaxDynamicSharedMemorySize,
                         GEMM_SMEM);
    gemm_tf32<1><<<dim3(CC/128, MM/128), 256, GEMM_SMEM>>>(
        out, nullptr, nullptr, MM, CC, CC);
}